// round 13
// baseline (speedup 1.0000x reference)
#include <cuda_runtime.h>
#include <math.h>
#include <stdint.h>

#define H 2048
#define NH 16
#define HD 128
#define SEQ 2048
#define BATCH 2
#define NQKV (H + 2*HD)   // 2304
#define SCALE 0.08838834764831843f  // 1/sqrt(128)
#define MROWS (BATCH*SEQ)

// ---------------- global scratch (allocation-free rule) ----------------
__device__ float    g_qkv[(size_t)MROWS * NQKV];   // tf32-rounded qkv
__device__ float    g_attn[(size_t)MROWS * H];     // tf32-rounded attn out
__device__ uint32_t g_xt[(size_t)MROWS * H];       // x, tf32-rounded
__device__ uint32_t g_wqt[(size_t)NQKV * H];       // Wqkv^T [N][K] rounded
__device__ uint32_t g_wpt[(size_t)H * H];          // Wproj^T [N][K] rounded

// ---------------- helpers ----------------
__device__ __forceinline__ uint32_t f2tf32(float x) {
    uint32_t r;
    asm("cvt.rna.tf32.f32 %0, %1;" : "=r"(r) : "f"(x));
    return r;
}
__device__ __forceinline__ void mma8(float* c, uint32_t a0, uint32_t a1,
                                     uint32_t a2, uint32_t a3,
                                     uint32_t b0, uint32_t b1) {
    asm volatile(
        "mma.sync.aligned.m16n8k8.row.col.f32.tf32.tf32.f32 "
        "{%0,%1,%2,%3}, {%4,%5,%6,%7}, {%8,%9}, {%0,%1,%2,%3};"
        : "+f"(c[0]), "+f"(c[1]), "+f"(c[2]), "+f"(c[3])
        : "r"(a0), "r"(a1), "r"(a2), "r"(a3), "r"(b0), "r"(b1));
}
__device__ __forceinline__ void ldsm4(uint32_t* r, uint32_t addr) {
    asm volatile("ldmatrix.sync.aligned.m8n8.x4.shared.b16 {%0,%1,%2,%3}, [%4];"
        : "=r"(r[0]), "=r"(r[1]), "=r"(r[2]), "=r"(r[3]) : "r"(addr));
}
__device__ __forceinline__ uint32_t sm_addr(const void* p) {
    return (uint32_t)__cvta_generic_to_shared(p);
}
__device__ __forceinline__ void cp16(uint32_t dst, const void* src) {
    asm volatile("cp.async.cg.shared.global [%0], [%1], 16;" :: "r"(dst), "l"(src));
}
__device__ __forceinline__ void cp_commit() {
    asm volatile("cp.async.commit_group;");
}
template<int N>
__device__ __forceinline__ void cp_wait() {
    asm volatile("cp.async.wait_group %0;" :: "n"(N));
}
__device__ __forceinline__ float fast_exp(float x) {
    float t = fmaxf(x * 1.4426950408889634f, -126.0f);
    float fl = floorf(t);
    float f = t - fl;
    float p =              1.535336188319500e-4f;
    p = fmaf(p, f, 1.339887440266574e-3f);
    p = fmaf(p, f, 9.618437357674640e-3f);
    p = fmaf(p, f, 5.550332471162809e-2f);
    p = fmaf(p, f, 2.402264791363012e-1f);
    p = fmaf(p, f, 6.931472028550421e-1f);
    p = fmaf(p, f, 1.0f);
    uint32_t sc = ((uint32_t)(int)(fl + 127.0f)) << 23;
    return p * __uint_as_float(sc);
}

// ---------------------------------------------------------------------------
// Pre-pass kernels
// ---------------------------------------------------------------------------
__global__ void __launch_bounds__(256) round_tf32(
    const float* __restrict__ in, uint32_t* __restrict__ out, int n4)
{
    int i = blockIdx.x * 256 + threadIdx.x;
    if (i >= n4) return;
    float4 v = ((const float4*)in)[i];
    uint4 t = {f2tf32(v.x), f2tf32(v.y), f2tf32(v.z), f2tf32(v.w)};
    ((uint4*)out)[i] = t;
}

__global__ void __launch_bounds__(256) transpose_round(
    const float* __restrict__ W, uint32_t* __restrict__ Wt, int K, int N)
{
    __shared__ float t[32][33];
    const int k0 = blockIdx.y * 32, n0 = blockIdx.x * 32;
    const int r = threadIdx.x >> 3, c4 = (threadIdx.x & 7) * 4;
    float4 v = *(const float4*)(W + (size_t)(k0 + r) * N + n0 + c4);
    t[r][c4] = v.x; t[r][c4+1] = v.y; t[r][c4+2] = v.z; t[r][c4+3] = v.w;
    __syncthreads();
    uint4 o = {f2tf32(t[c4][r]), f2tf32(t[c4+1][r]),
               f2tf32(t[c4+2][r]), f2tf32(t[c4+3][r])};
    *(uint4*)(Wt + (size_t)(n0 + r) * K + k0 + c4) = o;
}

// ---------------------------------------------------------------------------
// TF32 GEMM (round-12, unchanged): 256x128 tiles, 512 threads, 3-stage
// cp.async ring, one barrier per chunk, full-ldmatrix fragments.
// ---------------------------------------------------------------------------
#define GPQ 36
#define GSA (256 * GPQ)
#define GSB (128 * GPQ)
#define GST (GSA + GSB)
#define GEMM_SMEM_BYTES (3 * GST * 4)   // 165,888 B

template<bool ROUND_OUT>
__global__ void __launch_bounds__(512) gemm_tf32ca(
    const uint32_t* __restrict__ A, const uint32_t* __restrict__ Bt,
    const float* __restrict__ bias, float* __restrict__ C, int K, int N)
{
    extern __shared__ uint32_t sm[];
    const int tid  = threadIdx.x;
    const int warp = tid >> 5, lane = tid & 31;
    const int wm = warp >> 1, wn = warp & 1;
    const int g  = lane >> 2, tg = lane & 3;
    const int m0 = blockIdx.y * 256;
    const int n0 = blockIdx.x * 128;
    const uint32_t smb = sm_addr(sm);

    const int l15 = lane & 15;
    const int ahalfb = (lane >> 4) * 16;
    uint32_t aA[2];
    #pragma unroll
    for (int mt = 0; mt < 2; mt++)
        aA[mt] = smb + ((wm * 32 + mt * 16 + l15) * GPQ) * 4 + ahalfb;
    const int brow = (lane & 7) + ((lane >> 4) & 1) * 8;
    const int bcolb = ((lane >> 3) & 1) * 16;
    uint32_t bA[4];
    #pragma unroll
    for (int p = 0; p < 4; p++)
        bA[p] = smb + (GSA + (wn * 64 + p * 16 + brow) * GPQ) * 4 + bcolb;

    const int sr = tid >> 3, ss = (tid & 7) * 4;

    float acc[2][8][4];
    #pragma unroll
    for (int i = 0; i < 2; i++)
        #pragma unroll
        for (int j = 0; j < 8; j++)
            #pragma unroll
            for (int c = 0; c < 4; c++) acc[i][j][c] = 0.f;

    const int nkc = K / 32;
    #pragma unroll
    for (int s = 0; s < 2; s++) {
        const uint32_t off = s * GST * 4;
        #pragma unroll
        for (int i = 0; i < 4; i++) {
            const int row = sr + 64 * i;
            cp16(smb + off + (row * GPQ + ss) * 4,
                 A + (size_t)(m0 + row) * K + s * 32 + ss);
        }
        #pragma unroll
        for (int i = 0; i < 2; i++) {
            const int row = sr + 64 * i;
            cp16(smb + off + (GSA + row * GPQ + ss) * 4,
                 Bt + (size_t)(n0 + row) * K + s * 32 + ss);
        }
        cp_commit();
    }

    for (int kc = 0; kc < nkc; kc++) {
        const uint32_t soff = (uint32_t)(kc % 3) * GST * 4;
        if (kc + 1 < nkc) cp_wait<1>();
        else              cp_wait<0>();
        __syncthreads();

        if (kc + 2 < nkc) {
            const uint32_t noff = (uint32_t)((kc + 2) % 3) * GST * 4;
            #pragma unroll
            for (int i = 0; i < 4; i++) {
                const int row = sr + 64 * i;
                cp16(smb + noff + (row * GPQ + ss) * 4,
                     A + (size_t)(m0 + row) * K + (kc + 2) * 32 + ss);
            }
            #pragma unroll
            for (int i = 0; i < 2; i++) {
                const int row = sr + 64 * i;
                cp16(smb + noff + (GSA + row * GPQ + ss) * 4,
                     Bt + (size_t)(n0 + row) * K + (kc + 2) * 32 + ss);
            }
            cp_commit();
        }

        #pragma unroll
        for (int ks = 0; ks < 4; ks++) {
            uint32_t a[2][4], b[4][4];
            #pragma unroll
            for (int mt = 0; mt < 2; mt++)
                ldsm4(a[mt], aA[mt] + soff + ks * 32);
            #pragma unroll
            for (int p = 0; p < 4; p++)
                ldsm4(b[p], bA[p] + soff + ks * 32);
            #pragma unroll
            for (int mt = 0; mt < 2; mt++)
                #pragma unroll
                for (int nt = 0; nt < 8; nt++)
                    mma8(acc[mt][nt], a[mt][0], a[mt][1], a[mt][2], a[mt][3],
                         b[nt >> 1][(nt & 1) * 2], b[nt >> 1][(nt & 1) * 2 + 1]);
        }
    }

    #pragma unroll
    for (int nt = 0; nt < 8; nt++) {
        const int col = n0 + wn * 64 + nt * 8 + 2 * tg;
        float2 bv = *(const float2*)(bias + col);
        #pragma unroll
        for (int mt = 0; mt < 2; mt++) {
            const int row0 = m0 + wm * 32 + mt * 16 + g;
            float v0 = acc[mt][nt][0] + bv.x, v1 = acc[mt][nt][1] + bv.y;
            float v2 = acc[mt][nt][2] + bv.x, v3 = acc[mt][nt][3] + bv.y;
            if (ROUND_OUT) {
                v0 = __uint_as_float(f2tf32(v0));
                v1 = __uint_as_float(f2tf32(v1));
                v2 = __uint_as_float(f2tf32(v2));
                v3 = __uint_as_float(f2tf32(v3));
            }
            *(float2*)(C + (size_t)row0 * N + col)       = make_float2(v0, v1);
            *(float2*)(C + (size_t)(row0 + 8) * N + col) = make_float2(v2, v3);
        }
    }
}

// ---------------------------------------------------------------------------
// Causal MQA flash attention: BQ=64 x BK=32, 256 threads (warps 4x2,
// warp tile 16x16 S / 16x64 PV). smem 78KB -> 2 CTAs/SM (16 warps),
// double the round-12 occupancy. cp.async in-place prefetch as before.
// ---------------------------------------------------------------------------
#define PQ 132
#define PV 136
#define PS 36

#define OFF_Q 0
#define OFF_K (OFF_Q + 64*PQ)
#define OFF_V (OFF_K + 32*PQ)
#define OFF_S (OFF_V + 32*PV)
#define OFF_M (OFF_S + 64*PS)
#define ATTN_U32 (OFF_M + 3*64)
#define ATTN_SMEM_BYTES (ATTN_U32 * 4)    // 78,080 B -> 2 CTAs/SM

__global__ void __launch_bounds__(256) mqa_attn_tf32(
    const float* __restrict__ qkv, float* __restrict__ out)
{
    extern __shared__ uint32_t smem_u[];
    uint32_t* Qs = smem_u + OFF_Q;
    uint32_t* Ks = smem_u + OFF_K;
    uint32_t* Vs = smem_u + OFF_V;
    float*    Sf = (float*)(smem_u + OFF_S);
    uint32_t* Su = smem_u + OFF_S;
    float* m_s = (float*)(smem_u + OFF_M);
    float* l_s = m_s + 64;
    float* f_s = l_s + 64;

    const int tid  = threadIdx.x;
    const int warp = tid >> 5, lane = tid & 31;
    const int g = lane >> 2, tg = lane & 3;
    const int wm = warp >> 1, wn = warp & 1;     // 4 x 2 warp grid
    const int qt = gridDim.x - 1 - blockIdx.x;   // heavy blocks first
    const int h = blockIdx.y, b = blockIdx.z;
    const int q0 = qt * 64;

    const float* qbase = qkv + (size_t)b * SEQ * NQKV + h * HD;
    const float* kbase = qkv + (size_t)b * SEQ * NQKV + H;
    const float* vbase = kbase + HD;

    const int l15 = lane & 15;
    const int ahalfb = (lane >> 4) * 16;
    const int brow  = (lane & 7) + ((lane >> 4) & 1) * 8;
    const int bcolb = ((lane >> 3) & 1) * 16;
    // a-frags: Q rows wm*16.., P rows wm*16..; b-frags: K rows wn*16..
    const uint32_t qA = sm_addr(Qs) + ((wm * 16 + l15) * PQ) * 4 + ahalfb;
    const uint32_t pA = sm_addr(Su) + ((wm * 16 + l15) * PS) * 4 + ahalfb;
    const uint32_t kA = sm_addr(Ks) + ((wn * 16 + brow) * PQ) * 4 + bcolb;

    // prologue: Q (group 0, 2048 cp16), K0 (group 1, 1024), V0 (group 2, 1024)
    #pragma unroll
    for (int i = 0; i < 8; i++) {
        const int idx = tid + i * 256;
        const int r = idx >> 5, sg = (idx & 31) * 4;
        cp16(sm_addr(Qs) + (r * PQ + sg) * 4, qbase + (size_t)(q0 + r) * NQKV + sg);
    }
    cp_commit();
    #pragma unroll
    for (int i = 0; i < 4; i++) {
        const int idx = tid + i * 256;
        const int r = idx >> 5, sg = (idx & 31) * 4;
        cp16(sm_addr(Ks) + (r * PQ + sg) * 4, kbase + (size_t)r * NQKV + sg);
    }
    cp_commit();
    #pragma unroll
    for (int i = 0; i < 4; i++) {
        const int idx = tid + i * 256;
        const int r = idx >> 5, sg = (idx & 31) * 4;
        cp16(sm_addr(Vs) + (r * PV + sg) * 4, vbase + (size_t)r * NQKV + sg);
    }
    cp_commit();

    if (tid < 64) { m_s[tid] = -1e30f; l_s[tid] = 0.f; }

    float o[8][4];
    #pragma unroll
    for (int nt = 0; nt < 8; nt++)
        #pragma unroll
        for (int c = 0; c < 4; c++) o[nt][c] = 0.f;

    const int nkt = 2 * qt + 2;
    for (int kt = 0; kt < nkt; kt++) {
        const int k0 = kt * 32;
        cp_wait<1>();        // K(kt) arrived (V(kt) may still be in flight)
        __syncthreads();

        // ---- S = Q @ K^T (64x32), warp tile 16x16, 16 k8-steps ----
        float sacc[2][4];
        #pragma unroll
        for (int nt = 0; nt < 2; nt++)
            #pragma unroll
            for (int c = 0; c < 4; c++) sacc[nt][c] = 0.f;

        #pragma unroll
        for (int ks = 0; ks < 16; ks++) {
            uint32_t a[4], b01[4];
            ldsm4(a, qA + ks * 32);
            ldsm4(b01, kA + ks * 32);
            mma8(sacc[0], a[0], a[1], a[2], a[3], b01[0], b01[1]);
            mma8(sacc[1], a[0], a[1], a[2], a[3], b01[2], b01[3]);
        }

        const bool need_mask = (k0 + 31 > q0 + wm * 16);
        {
            const int mb = wm * 16;
            #pragma unroll
            for (int nt = 0; nt < 2; nt++) {
                const int nb = wn * 16 + nt * 8;
                const int c0 = nb + 2 * tg, c1 = c0 + 1;
                const int r0 = mb + g, r1 = mb + g + 8;
                float s00 = sacc[nt][0] * SCALE;
                float s01 = sacc[nt][1] * SCALE;
                float s10 = sacc[nt][2] * SCALE;
                float s11 = sacc[nt][3] * SCALE;
                if (need_mask) {
                    if (k0 + c0 > q0 + r0) s00 = -1e30f;
                    if (k0 + c1 > q0 + r0) s01 = -1e30f;
                    if (k0 + c0 > q0 + r1) s10 = -1e30f;
                    if (k0 + c1 > q0 + r1) s11 = -1e30f;
                }
                Sf[r0*PS + c0] = s00;  Sf[r0*PS + c1] = s01;
                Sf[r1*PS + c0] = s10;  Sf[r1*PS + c1] = s11;
            }
        }
        __syncthreads();

        // prefetch next K (overlaps softmax + PV)
        if (kt + 1 < nkt) {
            #pragma unroll
            for (int i = 0; i < 4; i++) {
                const int idx = tid + i * 256;
                const int r = idx >> 5, sg = (idx & 31) * 4;
                cp16(sm_addr(Ks) + (r * PQ + sg) * 4,
                     kbase + (size_t)(k0 + 32 + r) * NQKV + sg);
            }
            cp_commit();
        }

        // ---- online softmax: 4 threads/row over 32 cols; P -> tf32 ----
        {
            const int row = tid >> 2, sub = tid & 3;
            float* srow = Sf + row*PS + sub*8;
            uint32_t* urow = Su + row*PS + sub*8;
            float mold = m_s[row];
            float4 t0 = *(float4*)&srow[0];
            float4 t1 = *(float4*)&srow[4];
            float mx = fmaxf(fmaxf(fmaxf(t0.x, t0.y), fmaxf(t0.z, t0.w)),
                             fmaxf(fmaxf(t1.x, t1.y), fmaxf(t1.z, t1.w)));
            mx = fmaxf(mx, mold);
            mx = fmaxf(mx, __shfl_xor_sync(0xffffffffu, mx, 1));
            mx = fmaxf(mx, __shfl_xor_sync(0xffffffffu, mx, 2));
            float p0 = fast_exp(t0.x - mx), p1 = fast_exp(t0.y - mx);
            float p2 = fast_exp(t0.z - mx), p3 = fast_exp(t0.w - mx);
            float p4 = fast_exp(t1.x - mx), p5 = fast_exp(t1.y - mx);
            float p6 = fast_exp(t1.z - mx), p7 = fast_exp(t1.w - mx);
            float sum = ((p0 + p1) + (p2 + p3)) + ((p4 + p5) + (p6 + p7));
            uint4 u0 = {f2tf32(p0), f2tf32(p1), f2tf32(p2), f2tf32(p3)};
            uint4 u1 = {f2tf32(p4), f2tf32(p5), f2tf32(p6), f2tf32(p7)};
            *(uint4*)&urow[0] = u0;
            *(uint4*)&urow[4] = u1;
            sum += __shfl_xor_sync(0xffffffffu, sum, 1);
            sum += __shfl_xor_sync(0xffffffffu, sum, 2);
            if (sub == 0) {
                float f = fast_exp(mold - mx);
                l_s[row] = l_s[row] * f + sum;
                m_s[row] = mx;
                f_s[row] = f;
            }
        }
        if (kt + 1 < nkt) cp_wait<1>();   // V(kt) arrived (K(kt+1) in flight)
        else              cp_wait<0>();
        __syncthreads();

        // ---- O = O*f + P @ V (64x128), warp tile 16x64, 4 k8-steps ----
        float f0, f1;
        {
            const int mb = wm * 16;
            f0 = f_s[mb + g];
            f1 = f_s[mb + g + 8];
        }
        #pragma unroll
        for (int nt = 0; nt < 8; nt++) {
            o[nt][0] *= f0;  o[nt][1] *= f0;
            o[nt][2] *= f1;  o[nt][3] *= f1;
        }

        #pragma unroll
        for (int ks = 0; ks < 4; ks++) {
            const int kb = ks * 8;
            uint32_t a[4];
            ldsm4(a, pA + ks * 32);
            #pragma unroll
            for (int nt = 0; nt < 8; nt++) {
                const int nb = wn * 64 + nt * 8;
                uint32_t b0 = Vs[(kb + tg    )*PV + nb + g];
                uint32_t b1 = Vs[(kb + tg + 4)*PV + nb + g];
                mma8(o[nt], a[0], a[1], a[2], a[3], b0, b1);
            }
        }
        __syncthreads();

        // prefetch next V (overlaps next S-phase)
        if (kt + 1 < nkt) {
            #pragma unroll
            for (int i = 0; i < 4; i++) {
                const int idx = tid + i * 256;
                const int r = idx >> 5, sg = (idx & 31) * 4;
                cp16(sm_addr(Vs) + (r * PV + sg) * 4,
                     vbase + (size_t)(k0 + 32 + r) * NQKV + sg);
            }
            cp_commit();
        }
    }

    // final write: o / l, tf32-rounded for the proj GEMM's raw-bits path
    {
        const int mb = wm * 16;
        const float inv0 = 1.f / l_s[mb + g];
        const float inv1 = 1.f / l_s[mb + g + 8];
        #pragma unroll
        for (int nt = 0; nt < 8; nt++) {
            const int col = wn * 64 + nt * 8 + 2 * tg;
            size_t row0 = (size_t)(b * SEQ + q0 + mb + g) * H + h * HD + col;
            size_t row1 = (size_t)(b * SEQ + q0 + mb + g + 8) * H + h * HD + col;
            float2 r0 = {__uint_as_float(f2tf32(o[nt][0] * inv0)),
                         __uint_as_float(f2tf32(o[nt][1] * inv0))};
            float2 r1 = {__uint_as_float(f2tf32(o[nt][2] * inv1)),
                         __uint_as_float(f2tf32(o[nt][3] * inv1))};
            *(float2*)(out + row0) = r0;
            *(float2*)(out + row1) = r1;
        }
    }
}

// ---------------------------------------------------------------------------

extern "C" void kernel_launch(void* const* d_in, const int* in_sizes, int n_in,
                              void* d_out, int out_size)
{
    (void)in_sizes; (void)n_in; (void)out_size;
    const float* x     = (const float*)d_in[0];
    const float* Wqkv  = (const float*)d_in[1];
    const float* bqkv  = (const float*)d_in[2];
    const float* Wproj = (const float*)d_in[3];
    const float* bproj = (const float*)d_in[4];
    float* out = (float*)d_out;

    float *qkv_p, *attn_p;
    uint32_t *xt, *wqt, *wpt;
    cudaGetSymbolAddress((void**)&qkv_p, g_qkv);
    cudaGetSymbolAddress((void**)&attn_p, g_attn);
    cudaGetSymbolAddress((void**)&xt, g_xt);
    cudaGetSymbolAddress((void**)&wqt, g_wqt);
    cudaGetSymbolAddress((void**)&wpt, g_wpt);

    cudaFuncSetAttribute(mqa_attn_tf32, cudaFuncAttributeMaxDynamicSharedMemorySize,
                         ATTN_SMEM_BYTES);
    cudaFuncSetAttribute(gemm_tf32ca<true>, cudaFuncAttributeMaxDynamicSharedMemorySize,
                         GEMM_SMEM_BYTES);
    cudaFuncSetAttribute(gemm_tf32ca<false>, cudaFuncAttributeMaxDynamicSharedMemorySize,
                         GEMM_SMEM_BYTES);

    // 0) pre-round + pre-transpose
    round_tf32<<<(MROWS * H / 4 + 255) / 256, 256>>>(x, xt, MROWS * H / 4);
    transpose_round<<<dim3(NQKV / 32, H / 32), 256>>>(Wqkv, wqt, H, NQKV);
    transpose_round<<<dim3(H / 32, H / 32), 256>>>(Wproj, wpt, H, H);

    // 1) QKV GEMM (256x128 tiles, 3-stage cp.async; output tf32-rounded)
    gemm_tf32ca<true><<<dim3(NQKV / 128, MROWS / 256), 512, GEMM_SMEM_BYTES>>>(
        xt, wqt, bqkv, qkv_p, H, NQKV);

    // 2) causal MQA flash attention (BQ=64 x BK=32, 2 CTAs/SM)
    mqa_attn_tf32<<<dim3(SEQ / 64, NH, BATCH), 256, ATTN_SMEM_BYTES>>>(qkv_p, attn_p);

    // 3) proj GEMM -> d_out (fp32 output, no rounding)
    gemm_tf32ca<false><<<dim3(H / 128, MROWS / 256), 512, GEMM_SMEM_BYTES>>>(
        (const uint32_t*)attn_p, wpt, bproj, out, H, H);
}

// round 14
// speedup vs baseline: 1.0008x; 1.0008x over previous
#include <cuda_runtime.h>
#include <math.h>
#include <stdint.h>

#define H 2048
#define NH 16
#define HD 128
#define SEQ 2048
#define BATCH 2
#define NQKV (H + 2*HD)   // 2304
#define SCALE 0.08838834764831843f  // 1/sqrt(128)
#define MROWS (BATCH*SEQ)

// ---------------- global scratch (allocation-free rule) ----------------
__device__ float    g_qkv[(size_t)MROWS * NQKV];   // tf32-rounded qkv
__device__ float    g_attn[(size_t)MROWS * H];     // tf32-rounded attn out
__device__ uint32_t g_xt[(size_t)MROWS * H];       // x, tf32-rounded
__device__ uint32_t g_wqt[(size_t)NQKV * H];       // Wqkv^T [N][K] rounded
__device__ uint32_t g_wpt[(size_t)H * H];          // Wproj^T [N][K] rounded

// ---------------- helpers ----------------
__device__ __forceinline__ uint32_t f2tf32(float x) {
    uint32_t r;
    asm("cvt.rna.tf32.f32 %0, %1;" : "=r"(r) : "f"(x));
    return r;
}
__device__ __forceinline__ void mma8(float* c, uint32_t a0, uint32_t a1,
                                     uint32_t a2, uint32_t a3,
                                     uint32_t b0, uint32_t b1) {
    asm volatile(
        "mma.sync.aligned.m16n8k8.row.col.f32.tf32.tf32.f32 "
        "{%0,%1,%2,%3}, {%4,%5,%6,%7}, {%8,%9}, {%0,%1,%2,%3};"
        : "+f"(c[0]), "+f"(c[1]), "+f"(c[2]), "+f"(c[3])
        : "r"(a0), "r"(a1), "r"(a2), "r"(a3), "r"(b0), "r"(b1));
}
__device__ __forceinline__ void ldsm4(uint32_t* r, uint32_t addr) {
    asm volatile("ldmatrix.sync.aligned.m8n8.x4.shared.b16 {%0,%1,%2,%3}, [%4];"
        : "=r"(r[0]), "=r"(r[1]), "=r"(r[2]), "=r"(r[3]) : "r"(addr));
}
__device__ __forceinline__ uint32_t sm_addr(const void* p) {
    return (uint32_t)__cvta_generic_to_shared(p);
}
__device__ __forceinline__ void cp16(uint32_t dst, const void* src) {
    asm volatile("cp.async.cg.shared.global [%0], [%1], 16;" :: "r"(dst), "l"(src));
}
__device__ __forceinline__ void cp_commit() {
    asm volatile("cp.async.commit_group;");
}
template<int N>
__device__ __forceinline__ void cp_wait() {
    asm volatile("cp.async.wait_group %0;" :: "n"(N));
}
__device__ __forceinline__ float fast_exp(float x) {
    float t = fmaxf(x * 1.4426950408889634f, -126.0f);
    float fl = floorf(t);
    float f = t - fl;
    float p =              1.535336188319500e-4f;
    p = fmaf(p, f, 1.339887440266574e-3f);
    p = fmaf(p, f, 9.618437357674640e-3f);
    p = fmaf(p, f, 5.550332471162809e-2f);
    p = fmaf(p, f, 2.402264791363012e-1f);
    p = fmaf(p, f, 6.931472028550421e-1f);
    p = fmaf(p, f, 1.0f);
    uint32_t sc = ((uint32_t)(int)(fl + 127.0f)) << 23;
    return p * __uint_as_float(sc);
}

// ---------------------------------------------------------------------------
// Pre-pass kernels
// ---------------------------------------------------------------------------
__global__ void __launch_bounds__(256) round_tf32(
    const float* __restrict__ in, uint32_t* __restrict__ out, int n4)
{
    int i = blockIdx.x * 256 + threadIdx.x;
    if (i >= n4) return;
    float4 v = ((const float4*)in)[i];
    uint4 t = {f2tf32(v.x), f2tf32(v.y), f2tf32(v.z), f2tf32(v.w)};
    ((uint4*)out)[i] = t;
}

__global__ void __launch_bounds__(256) transpose_round(
    const float* __restrict__ W, uint32_t* __restrict__ Wt, int K, int N)
{
    __shared__ float t[32][33];
    const int k0 = blockIdx.y * 32, n0 = blockIdx.x * 32;
    const int r = threadIdx.x >> 3, c4 = (threadIdx.x & 7) * 4;
    float4 v = *(const float4*)(W + (size_t)(k0 + r) * N + n0 + c4);
    t[r][c4] = v.x; t[r][c4+1] = v.y; t[r][c4+2] = v.z; t[r][c4+3] = v.w;
    __syncthreads();
    uint4 o = {f2tf32(t[c4][r]), f2tf32(t[c4+1][r]),
               f2tf32(t[c4+2][r]), f2tf32(t[c4+3][r])};
    *(uint4*)(Wt + (size_t)(n0 + r) * K + k0 + c4) = o;
}

// ---------------------------------------------------------------------------
// TF32 GEMM (round-12, unchanged): 256x128 tiles, 512 threads, 3-stage
// cp.async ring, one barrier per chunk, full-ldmatrix fragments.
// ---------------------------------------------------------------------------
#define GPQ 36
#define GSA (256 * GPQ)
#define GSB (128 * GPQ)
#define GST (GSA + GSB)
#define GEMM_SMEM_BYTES (3 * GST * 4)   // 165,888 B

template<bool ROUND_OUT>
__global__ void __launch_bounds__(512) gemm_tf32ca(
    const uint32_t* __restrict__ A, const uint32_t* __restrict__ Bt,
    const float* __restrict__ bias, float* __restrict__ C, int K, int N)
{
    extern __shared__ uint32_t sm[];
    const int tid  = threadIdx.x;
    const int warp = tid >> 5, lane = tid & 31;
    const int wm = warp >> 1, wn = warp & 1;
    const int g  = lane >> 2, tg = lane & 3;
    const int m0 = blockIdx.y * 256;
    const int n0 = blockIdx.x * 128;
    const uint32_t smb = sm_addr(sm);

    const int l15 = lane & 15;
    const int ahalfb = (lane >> 4) * 16;
    uint32_t aA[2];
    #pragma unroll
    for (int mt = 0; mt < 2; mt++)
        aA[mt] = smb + ((wm * 32 + mt * 16 + l15) * GPQ) * 4 + ahalfb;
    const int brow = (lane & 7) + ((lane >> 4) & 1) * 8;
    const int bcolb = ((lane >> 3) & 1) * 16;
    uint32_t bA[4];
    #pragma unroll
    for (int p = 0; p < 4; p++)
        bA[p] = smb + (GSA + (wn * 64 + p * 16 + brow) * GPQ) * 4 + bcolb;

    const int sr = tid >> 3, ss = (tid & 7) * 4;

    float acc[2][8][4];
    #pragma unroll
    for (int i = 0; i < 2; i++)
        #pragma unroll
        for (int j = 0; j < 8; j++)
            #pragma unroll
            for (int c = 0; c < 4; c++) acc[i][j][c] = 0.f;

    const int nkc = K / 32;
    #pragma unroll
    for (int s = 0; s < 2; s++) {
        const uint32_t off = s * GST * 4;
        #pragma unroll
        for (int i = 0; i < 4; i++) {
            const int row = sr + 64 * i;
            cp16(smb + off + (row * GPQ + ss) * 4,
                 A + (size_t)(m0 + row) * K + s * 32 + ss);
        }
        #pragma unroll
        for (int i = 0; i < 2; i++) {
            const int row = sr + 64 * i;
            cp16(smb + off + (GSA + row * GPQ + ss) * 4,
                 Bt + (size_t)(n0 + row) * K + s * 32 + ss);
        }
        cp_commit();
    }

    for (int kc = 0; kc < nkc; kc++) {
        const uint32_t soff = (uint32_t)(kc % 3) * GST * 4;
        if (kc + 1 < nkc) cp_wait<1>();
        else              cp_wait<0>();
        __syncthreads();

        if (kc + 2 < nkc) {
            const uint32_t noff = (uint32_t)((kc + 2) % 3) * GST * 4;
            #pragma unroll
            for (int i = 0; i < 4; i++) {
                const int row = sr + 64 * i;
                cp16(smb + noff + (row * GPQ + ss) * 4,
                     A + (size_t)(m0 + row) * K + (kc + 2) * 32 + ss);
            }
            #pragma unroll
            for (int i = 0; i < 2; i++) {
                const int row = sr + 64 * i;
                cp16(smb + noff + (GSA + row * GPQ + ss) * 4,
                     Bt + (size_t)(n0 + row) * K + (kc + 2) * 32 + ss);
            }
            cp_commit();
        }

        #pragma unroll
        for (int ks = 0; ks < 4; ks++) {
            uint32_t a[2][4], b[4][4];
            #pragma unroll
            for (int mt = 0; mt < 2; mt++)
                ldsm4(a[mt], aA[mt] + soff + ks * 32);
            #pragma unroll
            for (int p = 0; p < 4; p++)
                ldsm4(b[p], bA[p] + soff + ks * 32);
            #pragma unroll
            for (int mt = 0; mt < 2; mt++)
                #pragma unroll
                for (int nt = 0; nt < 8; nt++)
                    mma8(acc[mt][nt], a[mt][0], a[mt][1], a[mt][2], a[mt][3],
                         b[nt >> 1][(nt & 1) * 2], b[nt >> 1][(nt & 1) * 2 + 1]);
        }
    }

    #pragma unroll
    for (int nt = 0; nt < 8; nt++) {
        const int col = n0 + wn * 64 + nt * 8 + 2 * tg;
        float2 bv = *(const float2*)(bias + col);
        #pragma unroll
        for (int mt = 0; mt < 2; mt++) {
            const int row0 = m0 + wm * 32 + mt * 16 + g;
            float v0 = acc[mt][nt][0] + bv.x, v1 = acc[mt][nt][1] + bv.y;
            float v2 = acc[mt][nt][2] + bv.x, v3 = acc[mt][nt][3] + bv.y;
            if (ROUND_OUT) {
                v0 = __uint_as_float(f2tf32(v0));
                v1 = __uint_as_float(f2tf32(v1));
                v2 = __uint_as_float(f2tf32(v2));
                v3 = __uint_as_float(f2tf32(v3));
            }
            *(float2*)(C + (size_t)row0 * N + col)       = make_float2(v0, v1);
            *(float2*)(C + (size_t)(row0 + 8) * N + col) = make_float2(v2, v3);
        }
    }
}

// ---------------------------------------------------------------------------
// Causal MQA flash attention: BQ=128 x BK=64 (round-12 tile), but with
// 512 threads / 16 warps: warp grid 8x2 (warp S tile 16x32, PV 16x64).
// Same smem (172 KB, 1 CTA/SM), same barrier count — double the warps to
// fill the tensor pipe during every phase. cp.async in-place prefetch.
// ---------------------------------------------------------------------------
#define PQ 132
#define PV 136
#define PS 68

#define OFF_Q 0
#define OFF_K (OFF_Q + 128*PQ)
#define OFF_V (OFF_K + 64*PQ)
#define OFF_S (OFF_V + 64*PV)
#define OFF_M (OFF_S + 128*PS)
#define ATTN_U32 (OFF_M + 3*128)
#define ATTN_SMEM_BYTES (ATTN_U32 * 4)    // 172,544 B

__global__ void __launch_bounds__(512) mqa_attn_tf32(
    const float* __restrict__ qkv, float* __restrict__ out)
{
    extern __shared__ uint32_t smem_u[];
    uint32_t* Qs = smem_u + OFF_Q;
    uint32_t* Ks = smem_u + OFF_K;
    uint32_t* Vs = smem_u + OFF_V;
    float*    Sf = (float*)(smem_u + OFF_S);
    uint32_t* Su = smem_u + OFF_S;
    float* m_s = (float*)(smem_u + OFF_M);
    float* l_s = m_s + 128;
    float* f_s = l_s + 128;

    const int tid  = threadIdx.x;
    const int warp = tid >> 5, lane = tid & 31;
    const int g = lane >> 2, tg = lane & 3;
    const int wm = warp >> 1, wn = warp & 1;     // 8 x 2 warp grid
    const int qt = gridDim.x - 1 - blockIdx.x;   // heavy blocks first
    const int h = blockIdx.y, b = blockIdx.z;
    const int q0 = qt * 128;

    const float* qbase = qkv + (size_t)b * SEQ * NQKV + h * HD;
    const float* kbase = qkv + (size_t)b * SEQ * NQKV + H;
    const float* vbase = kbase + HD;

    const int l15 = lane & 15;
    const int ahalfb = (lane >> 4) * 16;
    const int brow  = (lane & 7) + ((lane >> 4) & 1) * 8;
    const int bcolb = ((lane >> 3) & 1) * 16;
    // a-frags: 16 q-rows per warp (wm*16); b-frags: K rows wn*32..
    const uint32_t qA = sm_addr(Qs) + ((wm * 16 + l15) * PQ) * 4 + ahalfb;
    const uint32_t pA = sm_addr(Su) + ((wm * 16 + l15) * PS) * 4 + ahalfb;
    uint32_t kA[2];
    #pragma unroll
    for (int p = 0; p < 2; p++)
        kA[p] = sm_addr(Ks) + ((wn * 32 + p * 16 + brow) * PQ) * 4 + bcolb;

    // prologue: Q (group 0, 4096 cp16), K0 (group 1, 2048), V0 (group 2, 2048)
    #pragma unroll
    for (int i = 0; i < 8; i++) {
        const int idx = tid + i * 512;
        const int r = idx >> 5, sg = (idx & 31) * 4;
        cp16(sm_addr(Qs) + (r * PQ + sg) * 4, qbase + (size_t)(q0 + r) * NQKV + sg);
    }
    cp_commit();
    #pragma unroll
    for (int i = 0; i < 4; i++) {
        const int idx = tid + i * 512;
        const int r = idx >> 5, sg = (idx & 31) * 4;
        cp16(sm_addr(Ks) + (r * PQ + sg) * 4, kbase + (size_t)r * NQKV + sg);
    }
    cp_commit();
    #pragma unroll
    for (int i = 0; i < 4; i++) {
        const int idx = tid + i * 512;
        const int r = idx >> 5, sg = (idx & 31) * 4;
        cp16(sm_addr(Vs) + (r * PV + sg) * 4, vbase + (size_t)r * NQKV + sg);
    }
    cp_commit();

    if (tid < 128) { m_s[tid] = -1e30f; l_s[tid] = 0.f; }

    float o[8][4];
    #pragma unroll
    for (int nt = 0; nt < 8; nt++)
        #pragma unroll
        for (int c = 0; c < 4; c++) o[nt][c] = 0.f;

    const int nkt = 2 * qt + 2;
    for (int kt = 0; kt < nkt; kt++) {
        const int k0 = kt * 64;
        cp_wait<1>();        // K(kt) arrived (V(kt) may still be in flight)
        __syncthreads();

        // ---- S = Q @ K^T (128x64), warp tile 16x32, 16 k8-steps ----
        float sacc[4][4];
        #pragma unroll
        for (int nt = 0; nt < 4; nt++)
            #pragma unroll
            for (int c = 0; c < 4; c++) sacc[nt][c] = 0.f;

        #pragma unroll
        for (int ks = 0; ks < 16; ks++) {
            uint32_t a[4], b01[4], b23[4];
            ldsm4(a, qA + ks * 32);
            ldsm4(b01, kA[0] + ks * 32);
            ldsm4(b23, kA[1] + ks * 32);
            mma8(sacc[0], a[0], a[1], a[2], a[3], b01[0], b01[1]);
            mma8(sacc[1], a[0], a[1], a[2], a[3], b01[2], b01[3]);
            mma8(sacc[2], a[0], a[1], a[2], a[3], b23[0], b23[1]);
            mma8(sacc[3], a[0], a[1], a[2], a[3], b23[2], b23[3]);
        }

        // scale + (uniform-branch) causal mask + store S (fp32)
        const bool need_mask = (k0 + 63 > q0 + wm * 16);
        {
            const int mb = wm * 16;
            #pragma unroll
            for (int nt = 0; nt < 4; nt++) {
                const int nb = wn * 32 + nt * 8;
                const int c0 = nb + 2 * tg, c1 = c0 + 1;
                const int r0 = mb + g, r1 = mb + g + 8;
                float s00 = sacc[nt][0] * SCALE;
                float s01 = sacc[nt][1] * SCALE;
                float s10 = sacc[nt][2] * SCALE;
                float s11 = sacc[nt][3] * SCALE;
                if (need_mask) {
                    if (k0 + c0 > q0 + r0) s00 = -1e30f;
                    if (k0 + c1 > q0 + r0) s01 = -1e30f;
                    if (k0 + c0 > q0 + r1) s10 = -1e30f;
                    if (k0 + c1 > q0 + r1) s11 = -1e30f;
                }
                Sf[r0*PS + c0] = s00;  Sf[r0*PS + c1] = s01;
                Sf[r1*PS + c0] = s10;  Sf[r1*PS + c1] = s11;
            }
        }
        __syncthreads();

        // prefetch next K (overlaps softmax + PV)
        if (kt + 1 < nkt) {
            #pragma unroll
            for (int i = 0; i < 4; i++) {
                const int idx = tid + i * 512;
                const int r = idx >> 5, sg = (idx & 31) * 4;
                cp16(sm_addr(Ks) + (r * PQ + sg) * 4,
                     kbase + (size_t)(k0 + 64 + r) * NQKV + sg);
            }
            cp_commit();
        }

        // ---- online softmax: 4 threads/row (16 cols each); P -> tf32 ----
        {
            const int row = tid >> 2, sub = tid & 3;
            float* srow = Sf + row*PS + sub*16;
            uint32_t* urow = Su + row*PS + sub*16;
            float mold = m_s[row];
            float mx = mold;
            #pragma unroll
            for (int c = 0; c < 4; c++) {
                float4 t = *(float4*)&srow[4*c];
                mx = fmaxf(mx, fmaxf(fmaxf(t.x, t.y), fmaxf(t.z, t.w)));
            }
            mx = fmaxf(mx, __shfl_xor_sync(0xffffffffu, mx, 1));
            mx = fmaxf(mx, __shfl_xor_sync(0xffffffffu, mx, 2));
            float sum = 0.f;
            #pragma unroll
            for (int j = 0; j < 4; j++) {
                float4 t = *(float4*)&srow[4*j];
                float p0 = fast_exp(t.x - mx), p1 = fast_exp(t.y - mx);
                float p2 = fast_exp(t.z - mx), p3 = fast_exp(t.w - mx);
                sum += (p0 + p1) + (p2 + p3);
                uint4 u = {f2tf32(p0), f2tf32(p1), f2tf32(p2), f2tf32(p3)};
                *(uint4*)&urow[4*j] = u;
            }
            sum += __shfl_xor_sync(0xffffffffu, sum, 1);
            sum += __shfl_xor_sync(0xffffffffu, sum, 2);
            if (sub == 0) {
                float f = fast_exp(mold - mx);
                l_s[row] = l_s[row] * f + sum;
                m_s[row] = mx;
                f_s[row] = f;
            }
        }
        if (kt + 1 < nkt) cp_wait<1>();   // V(kt) arrived (K(kt+1) in flight)
        else              cp_wait<0>();
        __syncthreads();

        // ---- O = O*f + P @ V (128x128), warp tile 16x64, 8 k8-steps ----
        float f0, f1;
        {
            const int mb = wm * 16;
            f0 = f_s[mb + g];
            f1 = f_s[mb + g + 8];
        }
        #pragma unroll
        for (int nt = 0; nt < 8; nt++) {
            o[nt][0] *= f0;  o[nt][1] *= f0;
            o[nt][2] *= f1;  o[nt][3] *= f1;
        }

        #pragma unroll
        for (int ks = 0; ks < 8; ks++) {
            const int kb = ks * 8;
            uint32_t a[4];
            ldsm4(a, pA + ks * 32);
            #pragma unroll
            for (int nt = 0; nt < 8; nt++) {
                const int nb = wn * 64 + nt * 8;
                uint32_t b0 = Vs[(kb + tg    )*PV + nb + g];
                uint32_t b1 = Vs[(kb + tg + 4)*PV + nb + g];
                mma8(o[nt], a[0], a[1], a[2], a[3], b0, b1);
            }
        }
        __syncthreads();

        // prefetch next V (overlaps next S-phase)
        if (kt + 1 < nkt) {
            #pragma unroll
            for (int i = 0; i < 4; i++) {
                const int idx = tid + i * 512;
                const int r = idx >> 5, sg = (idx & 31) * 4;
                cp16(sm_addr(Vs) + (r * PV + sg) * 4,
                     vbase + (size_t)(k0 + 64 + r) * NQKV + sg);
            }
            cp_commit();
        }
    }

    // final write: o / l, tf32-rounded for the proj GEMM's raw-bits path
    {
        const int mb = wm * 16;
        const float inv0 = 1.f / l_s[mb + g];
        const float inv1 = 1.f / l_s[mb + g + 8];
        #pragma unroll
        for (int nt = 0; nt < 8; nt++) {
            const int col = wn * 64 + nt * 8 + 2 * tg;
            size_t row0 = (size_t)(b * SEQ + q0 + mb + g) * H + h * HD + col;
            size_t row1 = (size_t)(b * SEQ + q0 + mb + g + 8) * H + h * HD + col;
            float2 r0 = {__uint_as_float(f2tf32(o[nt][0] * inv0)),
                         __uint_as_float(f2tf32(o[nt][1] * inv0))};
            float2 r1 = {__uint_as_float(f2tf32(o[nt][2] * inv1)),
                         __uint_as_float(f2tf32(o[nt][3] * inv1))};
            *(float2*)(out + row0) = r0;
            *(float2*)(out + row1) = r1;
        }
    }
}

// ---------------------------------------------------------------------------

extern "C" void kernel_launch(void* const* d_in, const int* in_sizes, int n_in,
                              void* d_out, int out_size)
{
    (void)in_sizes; (void)n_in; (void)out_size;
    const float* x     = (const float*)d_in[0];
    const float* Wqkv  = (const float*)d_in[1];
    const float* bqkv  = (const float*)d_in[2];
    const float* Wproj = (const float*)d_in[3];
    const float* bproj = (const float*)d_in[4];
    float* out = (float*)d_out;

    float *qkv_p, *attn_p;
    uint32_t *xt, *wqt, *wpt;
    cudaGetSymbolAddress((void**)&qkv_p, g_qkv);
    cudaGetSymbolAddress((void**)&attn_p, g_attn);
    cudaGetSymbolAddress((void**)&xt, g_xt);
    cudaGetSymbolAddress((void**)&wqt, g_wqt);
    cudaGetSymbolAddress((void**)&wpt, g_wpt);

    cudaFuncSetAttribute(mqa_attn_tf32, cudaFuncAttributeMaxDynamicSharedMemorySize,
                         ATTN_SMEM_BYTES);
    cudaFuncSetAttribute(gemm_tf32ca<true>, cudaFuncAttributeMaxDynamicSharedMemorySize,
                         GEMM_SMEM_BYTES);
    cudaFuncSetAttribute(gemm_tf32ca<false>, cudaFuncAttributeMaxDynamicSharedMemorySize,
                         GEMM_SMEM_BYTES);

    // 0) pre-round + pre-transpose
    round_tf32<<<(MROWS * H / 4 + 255) / 256, 256>>>(x, xt, MROWS * H / 4);
    transpose_round<<<dim3(NQKV / 32, H / 32), 256>>>(Wqkv, wqt, H, NQKV);
    transpose_round<<<dim3(H / 32, H / 32), 256>>>(Wproj, wpt, H, H);

    // 1) QKV GEMM (256x128 tiles, 3-stage cp.async; output tf32-rounded)
    gemm_tf32ca<true><<<dim3(NQKV / 128, MROWS / 256), 512, GEMM_SMEM_BYTES>>>(
        xt, wqt, bqkv, qkv_p, H, NQKV);

    // 2) causal MQA flash attention (BQ=128 x BK=64, 512 threads / 16 warps)
    mqa_attn_tf32<<<dim3(SEQ / 128, NH, BATCH), 512, ATTN_SMEM_BYTES>>>(qkv_p, attn_p);

    // 3) proj GEMM -> d_out (fp32 output, no rounding)
    gemm_tf32ca<false><<<dim3(H / 128, MROWS / 256), 512, GEMM_SMEM_BYTES>>>(
        (const uint32_t*)attn_p, wpt, bproj, out, H, H);
}

// round 15
// speedup vs baseline: 1.0503x; 1.0495x over previous
#include <cuda_runtime.h>
#include <math.h>
#include <stdint.h>

#define H 2048
#define NH 16
#define HD 128
#define SEQ 2048
#define BATCH 2
#define NQKV (H + 2*HD)   // 2304
#define SCALE 0.08838834764831843f  // 1/sqrt(128)
#define MROWS (BATCH*SEQ)

// ---------------- global scratch (allocation-free rule) ----------------
__device__ float    g_qkv[(size_t)MROWS * NQKV];   // tf32-rounded qkv
__device__ float    g_attn[(size_t)MROWS * H];     // tf32-rounded attn out
__device__ uint32_t g_xt[(size_t)MROWS * H];       // x, tf32-rounded
__device__ uint32_t g_wqt[(size_t)NQKV * H];       // Wqkv^T [N][K] rounded
__device__ uint32_t g_wpt[(size_t)H * H];          // Wproj^T [N][K] rounded

// ---------------- helpers ----------------
__device__ __forceinline__ uint32_t f2tf32(float x) {
    uint32_t r;
    asm("cvt.rna.tf32.f32 %0, %1;" : "=r"(r) : "f"(x));
    return r;
}
__device__ __forceinline__ void mma8(float* c, uint32_t a0, uint32_t a1,
                                     uint32_t a2, uint32_t a3,
                                     uint32_t b0, uint32_t b1) {
    asm volatile(
        "mma.sync.aligned.m16n8k8.row.col.f32.tf32.tf32.f32 "
        "{%0,%1,%2,%3}, {%4,%5,%6,%7}, {%8,%9}, {%0,%1,%2,%3};"
        : "+f"(c[0]), "+f"(c[1]), "+f"(c[2]), "+f"(c[3])
        : "r"(a0), "r"(a1), "r"(a2), "r"(a3), "r"(b0), "r"(b1));
}
__device__ __forceinline__ void ldsm4(uint32_t* r, uint32_t addr) {
    asm volatile("ldmatrix.sync.aligned.m8n8.x4.shared.b16 {%0,%1,%2,%3}, [%4];"
        : "=r"(r[0]), "=r"(r[1]), "=r"(r[2]), "=r"(r[3]) : "r"(addr));
}
__device__ __forceinline__ uint32_t sm_addr(const void* p) {
    return (uint32_t)__cvta_generic_to_shared(p);
}
__device__ __forceinline__ void cp16(uint32_t dst, const void* src) {
    asm volatile("cp.async.cg.shared.global [%0], [%1], 16;" :: "r"(dst), "l"(src));
}
__device__ __forceinline__ void cp_commit() {
    asm volatile("cp.async.commit_group;");
}
template<int N>
__device__ __forceinline__ void cp_wait() {
    asm volatile("cp.async.wait_group %0;" :: "n"(N));
}
__device__ __forceinline__ void bar64(int id) {
    asm volatile("bar.sync %0, 64;" :: "r"(id) : "memory");
}
__device__ __forceinline__ float fast_exp(float x) {
    float t = fmaxf(x * 1.4426950408889634f, -126.0f);
    float fl = floorf(t);
    float f = t - fl;
    float p =              1.535336188319500e-4f;
    p = fmaf(p, f, 1.339887440266574e-3f);
    p = fmaf(p, f, 9.618437357674640e-3f);
    p = fmaf(p, f, 5.550332471162809e-2f);
    p = fmaf(p, f, 2.402264791363012e-1f);
    p = fmaf(p, f, 6.931472028550421e-1f);
    p = fmaf(p, f, 1.0f);
    uint32_t sc = ((uint32_t)(int)(fl + 127.0f)) << 23;
    return p * __uint_as_float(sc);
}

// ---------------------------------------------------------------------------
// Pre-pass kernels
// ---------------------------------------------------------------------------
__global__ void __launch_bounds__(256) round_tf32(
    const float* __restrict__ in, uint32_t* __restrict__ out, int n4)
{
    int i = blockIdx.x * 256 + threadIdx.x;
    if (i >= n4) return;
    float4 v = ((const float4*)in)[i];
    uint4 t = {f2tf32(v.x), f2tf32(v.y), f2tf32(v.z), f2tf32(v.w)};
    ((uint4*)out)[i] = t;
}

__global__ void __launch_bounds__(256) transpose_round(
    const float* __restrict__ W, uint32_t* __restrict__ Wt, int K, int N)
{
    __shared__ float t[32][33];
    const int k0 = blockIdx.y * 32, n0 = blockIdx.x * 32;
    const int r = threadIdx.x >> 3, c4 = (threadIdx.x & 7) * 4;
    float4 v = *(const float4*)(W + (size_t)(k0 + r) * N + n0 + c4);
    t[r][c4] = v.x; t[r][c4+1] = v.y; t[r][c4+2] = v.z; t[r][c4+3] = v.w;
    __syncthreads();
    uint4 o = {f2tf32(t[c4][r]), f2tf32(t[c4+1][r]),
               f2tf32(t[c4+2][r]), f2tf32(t[c4+3][r])};
    *(uint4*)(Wt + (size_t)(n0 + r) * K + k0 + c4) = o;
}

// ---------------------------------------------------------------------------
// TF32 GEMM (round-12, unchanged): 256x128 tiles, 512 threads, 3-stage
// cp.async ring, one barrier per chunk, full-ldmatrix fragments.
// ---------------------------------------------------------------------------
#define GPQ 36
#define GSA (256 * GPQ)
#define GSB (128 * GPQ)
#define GST (GSA + GSB)
#define GEMM_SMEM_BYTES (3 * GST * 4)   // 165,888 B

template<bool ROUND_OUT>
__global__ void __launch_bounds__(512) gemm_tf32ca(
    const uint32_t* __restrict__ A, const uint32_t* __restrict__ Bt,
    const float* __restrict__ bias, float* __restrict__ C, int K, int N)
{
    extern __shared__ uint32_t sm[];
    const int tid  = threadIdx.x;
    const int warp = tid >> 5, lane = tid & 31;
    const int wm = warp >> 1, wn = warp & 1;
    const int g  = lane >> 2, tg = lane & 3;
    const int m0 = blockIdx.y * 256;
    const int n0 = blockIdx.x * 128;
    const uint32_t smb = sm_addr(sm);

    const int l15 = lane & 15;
    const int ahalfb = (lane >> 4) * 16;
    uint32_t aA[2];
    #pragma unroll
    for (int mt = 0; mt < 2; mt++)
        aA[mt] = smb + ((wm * 32 + mt * 16 + l15) * GPQ) * 4 + ahalfb;
    const int brow = (lane & 7) + ((lane >> 4) & 1) * 8;
    const int bcolb = ((lane >> 3) & 1) * 16;
    uint32_t bA[4];
    #pragma unroll
    for (int p = 0; p < 4; p++)
        bA[p] = smb + (GSA + (wn * 64 + p * 16 + brow) * GPQ) * 4 + bcolb;

    const int sr = tid >> 3, ss = (tid & 7) * 4;

    float acc[2][8][4];
    #pragma unroll
    for (int i = 0; i < 2; i++)
        #pragma unroll
        for (int j = 0; j < 8; j++)
            #pragma unroll
            for (int c = 0; c < 4; c++) acc[i][j][c] = 0.f;

    const int nkc = K / 32;
    #pragma unroll
    for (int s = 0; s < 2; s++) {
        const uint32_t off = s * GST * 4;
        #pragma unroll
        for (int i = 0; i < 4; i++) {
            const int row = sr + 64 * i;
            cp16(smb + off + (row * GPQ + ss) * 4,
                 A + (size_t)(m0 + row) * K + s * 32 + ss);
        }
        #pragma unroll
        for (int i = 0; i < 2; i++) {
            const int row = sr + 64 * i;
            cp16(smb + off + (GSA + row * GPQ + ss) * 4,
                 Bt + (size_t)(n0 + row) * K + s * 32 + ss);
        }
        cp_commit();
    }

    for (int kc = 0; kc < nkc; kc++) {
        const uint32_t soff = (uint32_t)(kc % 3) * GST * 4;
        if (kc + 1 < nkc) cp_wait<1>();
        else              cp_wait<0>();
        __syncthreads();

        if (kc + 2 < nkc) {
            const uint32_t noff = (uint32_t)((kc + 2) % 3) * GST * 4;
            #pragma unroll
            for (int i = 0; i < 4; i++) {
                const int row = sr + 64 * i;
                cp16(smb + noff + (row * GPQ + ss) * 4,
                     A + (size_t)(m0 + row) * K + (kc + 2) * 32 + ss);
            }
            #pragma unroll
            for (int i = 0; i < 2; i++) {
                const int row = sr + 64 * i;
                cp16(smb + noff + (GSA + row * GPQ + ss) * 4,
                     Bt + (size_t)(n0 + row) * K + (kc + 2) * 32 + ss);
            }
            cp_commit();
        }

        #pragma unroll
        for (int ks = 0; ks < 4; ks++) {
            uint32_t a[2][4], b[4][4];
            #pragma unroll
            for (int mt = 0; mt < 2; mt++)
                ldsm4(a[mt], aA[mt] + soff + ks * 32);
            #pragma unroll
            for (int p = 0; p < 4; p++)
                ldsm4(b[p], bA[p] + soff + ks * 32);
            #pragma unroll
            for (int mt = 0; mt < 2; mt++)
                #pragma unroll
                for (int nt = 0; nt < 8; nt++)
                    mma8(acc[mt][nt], a[mt][0], a[mt][1], a[mt][2], a[mt][3],
                         b[nt >> 1][(nt & 1) * 2], b[nt >> 1][(nt & 1) * 2 + 1]);
        }
    }

    #pragma unroll
    for (int nt = 0; nt < 8; nt++) {
        const int col = n0 + wn * 64 + nt * 8 + 2 * tg;
        float2 bv = *(const float2*)(bias + col);
        #pragma unroll
        for (int mt = 0; mt < 2; mt++) {
            const int row0 = m0 + wm * 32 + mt * 16 + g;
            float v0 = acc[mt][nt][0] + bv.x, v1 = acc[mt][nt][1] + bv.y;
            float v2 = acc[mt][nt][2] + bv.x, v3 = acc[mt][nt][3] + bv.y;
            if (ROUND_OUT) {
                v0 = __uint_as_float(f2tf32(v0));
                v1 = __uint_as_float(f2tf32(v1));
                v2 = __uint_as_float(f2tf32(v2));
                v3 = __uint_as_float(f2tf32(v3));
            }
            *(float2*)(C + (size_t)row0 * N + col)       = make_float2(v0, v1);
            *(float2*)(C + (size_t)(row0 + 8) * N + col) = make_float2(v2, v3);
        }
    }
}

// ---------------------------------------------------------------------------
// Causal MQA flash attention: BQ=128 x BK=64, 256 threads (warps 4x2),
// round-12 tile, but IN-REGISTER pair-wide softmax:
//  - row-max exchanged between the two wn warps via tiny smem + bar.sync(64)
//  - exp applied directly to S accumulators; P (tf32) written once to smem
//  - raw-S store, softmax smem read-back and one full barrier eliminated.
// Per tile: 3 full barriers + 1 named-64 (was 4 full).
// ---------------------------------------------------------------------------
#define PQ 132
#define PV 136
#define PS 68

#define OFF_Q 0
#define OFF_K (OFF_Q + 128*PQ)
#define OFF_V (OFF_K + 64*PQ)
#define OFF_S (OFF_V + 64*PV)
#define OFF_M (OFF_S + 128*PS)
#define OFF_PMX (OFF_M + 2*128)          // pair max partials [2][128]
#define OFF_PSM (OFF_PMX + 2*128)        // pair sum partials [2][128]
#define ATTN_U32 (OFF_PSM + 2*128)
#define ATTN_SMEM_BYTES (ATTN_U32 * 4)   // ~174 KB

__global__ void __launch_bounds__(256) mqa_attn_tf32(
    const float* __restrict__ qkv, float* __restrict__ out)
{
    extern __shared__ uint32_t smem_u[];
    uint32_t* Qs = smem_u + OFF_Q;
    uint32_t* Ks = smem_u + OFF_K;
    uint32_t* Vs = smem_u + OFF_V;
    uint32_t* Su = smem_u + OFF_S;            // P (tf32 bits)
    float* m_s  = (float*)(smem_u + OFF_M);
    float* l_s  = m_s + 128;
    float* pmxS = (float*)(smem_u + OFF_PMX); // [wn][row]
    float* psmS = (float*)(smem_u + OFF_PSM); // [wn][row]

    const int tid  = threadIdx.x;
    const int warp = tid >> 5, lane = tid & 31;
    const int g = lane >> 2, tg = lane & 3;
    const int wm = warp >> 1, wn = warp & 1;     // 4 x 2 warp grid
    const int qt = gridDim.x - 1 - blockIdx.x;   // heavy blocks first
    const int h = blockIdx.y, b = blockIdx.z;
    const int q0 = qt * 128;

    const float* qbase = qkv + (size_t)b * SEQ * NQKV + h * HD;
    const float* kbase = qkv + (size_t)b * SEQ * NQKV + H;
    const float* vbase = kbase + HD;

    const int l15 = lane & 15;
    const int ahalfb = (lane >> 4) * 16;
    const int brow  = (lane & 7) + ((lane >> 4) & 1) * 8;
    const int bcolb = ((lane >> 3) & 1) * 16;
    uint32_t qA[2], pA[2], kA[2];
    #pragma unroll
    for (int mt = 0; mt < 2; mt++) {
        const int row = wm * 32 + mt * 16 + l15;
        qA[mt] = sm_addr(Qs) + (row * PQ) * 4 + ahalfb;
        pA[mt] = sm_addr(Su) + (row * PS) * 4 + ahalfb;
    }
    #pragma unroll
    for (int p = 0; p < 2; p++)
        kA[p] = sm_addr(Ks) + ((wn * 32 + p * 16 + brow) * PQ) * 4 + bcolb;

    // prologue: Q (group 0), K0 (group 1), V0 (group 2)
    #pragma unroll
    for (int i = 0; i < 16; i++) {
        const int idx = tid + i * 256;
        const int r = idx >> 5, sg = (idx & 31) * 4;
        cp16(sm_addr(Qs) + (r * PQ + sg) * 4, qbase + (size_t)(q0 + r) * NQKV + sg);
    }
    cp_commit();
    #pragma unroll
    for (int i = 0; i < 8; i++) {
        const int idx = tid + i * 256;
        const int r = idx >> 5, sg = (idx & 31) * 4;
        cp16(sm_addr(Ks) + (r * PQ + sg) * 4, kbase + (size_t)r * NQKV + sg);
    }
    cp_commit();
    #pragma unroll
    for (int i = 0; i < 8; i++) {
        const int idx = tid + i * 256;
        const int r = idx >> 5, sg = (idx & 31) * 4;
        cp16(sm_addr(Vs) + (r * PV + sg) * 4, vbase + (size_t)r * NQKV + sg);
    }
    cp_commit();

    if (tid < 128) { m_s[tid] = -1e30f; l_s[tid] = 0.f; }

    float o[2][8][4];
    #pragma unroll
    for (int mt = 0; mt < 2; mt++)
        #pragma unroll
        for (int nt = 0; nt < 8; nt++)
            #pragma unroll
            for (int c = 0; c < 4; c++) o[mt][nt][c] = 0.f;

    const int nkt = 2 * qt + 2;
    for (int kt = 0; kt < nkt; kt++) {
        const int k0 = kt * 64;
        cp_wait<1>();        // bar A: K(kt) done (V(kt) may be in flight)
        __syncthreads();

        // ---- S = Q @ K^T (128x64), warp tile 32x32, 16 k8-steps ----
        float sacc[2][4][4];
        #pragma unroll
        for (int mt = 0; mt < 2; mt++)
            #pragma unroll
            for (int nt = 0; nt < 4; nt++)
                #pragma unroll
                for (int c = 0; c < 4; c++) sacc[mt][nt][c] = 0.f;

        #pragma unroll
        for (int ks = 0; ks < 16; ks++) {
            uint32_t a[2][4], b01[4], b23[4];
            ldsm4(a[0], qA[0] + ks * 32);
            ldsm4(a[1], qA[1] + ks * 32);
            ldsm4(b01, kA[0] + ks * 32);
            ldsm4(b23, kA[1] + ks * 32);
            #pragma unroll
            for (int mt = 0; mt < 2; mt++) {
                mma8(sacc[mt][0], a[mt][0], a[mt][1], a[mt][2], a[mt][3], b01[0], b01[1]);
                mma8(sacc[mt][1], a[mt][0], a[mt][1], a[mt][2], a[mt][3], b01[2], b01[3]);
                mma8(sacc[mt][2], a[mt][0], a[mt][1], a[mt][2], a[mt][3], b23[0], b23[1]);
                mma8(sacc[mt][3], a[mt][0], a[mt][1], a[mt][2], a[mt][3], b23[2], b23[3]);
            }
        }

        // ---- scale + mask + in-register row-max partials ----
        const bool need_mask = (k0 + 63 > q0 + wm * 32);
        float pmax[2][2];
        #pragma unroll
        for (int mt = 0; mt < 2; mt++) { pmax[mt][0] = -1e30f; pmax[mt][1] = -1e30f; }
        #pragma unroll
        for (int mt = 0; mt < 2; mt++) {
            const int mb = wm * 32 + mt * 16;
            #pragma unroll
            for (int nt = 0; nt < 4; nt++) {
                const int nb = wn * 32 + nt * 8;
                const int c0 = nb + 2 * tg, c1 = c0 + 1;
                const int r0 = mb + g, r1 = mb + g + 8;
                float s00 = sacc[mt][nt][0] * SCALE;
                float s01 = sacc[mt][nt][1] * SCALE;
                float s10 = sacc[mt][nt][2] * SCALE;
                float s11 = sacc[mt][nt][3] * SCALE;
                if (need_mask) {
                    if (k0 + c0 > q0 + r0) s00 = -1e30f;
                    if (k0 + c1 > q0 + r0) s01 = -1e30f;
                    if (k0 + c0 > q0 + r1) s10 = -1e30f;
                    if (k0 + c1 > q0 + r1) s11 = -1e30f;
                }
                sacc[mt][nt][0] = s00;  sacc[mt][nt][1] = s01;
                sacc[mt][nt][2] = s10;  sacc[mt][nt][3] = s11;
                pmax[mt][0] = fmaxf(pmax[mt][0], fmaxf(s00, s01));
                pmax[mt][1] = fmaxf(pmax[mt][1], fmaxf(s10, s11));
            }
        }
        #pragma unroll
        for (int mt = 0; mt < 2; mt++) {
            pmax[mt][0] = fmaxf(pmax[mt][0], __shfl_xor_sync(0xffffffffu, pmax[mt][0], 1));
            pmax[mt][0] = fmaxf(pmax[mt][0], __shfl_xor_sync(0xffffffffu, pmax[mt][0], 2));
            pmax[mt][1] = fmaxf(pmax[mt][1], __shfl_xor_sync(0xffffffffu, pmax[mt][1], 1));
            pmax[mt][1] = fmaxf(pmax[mt][1], __shfl_xor_sync(0xffffffffu, pmax[mt][1], 2));
        }
        if (tg == 0) {
            #pragma unroll
            for (int mt = 0; mt < 2; mt++) {
                const int r = wm * 32 + mt * 16 + g;
                pmxS[wn * 128 + r]     = pmax[mt][0];
                pmxS[wn * 128 + r + 8] = pmax[mt][1];
            }
        }
        bar64(wm + 1);   // pair barrier: partials visible within warp pair

        // combine pair max with running max; per-lane f
        float mnew[2][2], fr[2][2];
        #pragma unroll
        for (int mt = 0; mt < 2; mt++) {
            const int r = wm * 32 + mt * 16 + g;
            float oth0 = pmxS[(1 - wn) * 128 + r];
            float oth1 = pmxS[(1 - wn) * 128 + r + 8];
            float mold0 = m_s[r], mold1 = m_s[r + 8];
            mnew[mt][0] = fmaxf(fmaxf(pmax[mt][0], oth0), mold0);
            mnew[mt][1] = fmaxf(fmaxf(pmax[mt][1], oth1), mold1);
            fr[mt][0] = fast_exp(mold0 - mnew[mt][0]);
            fr[mt][1] = fast_exp(mold1 - mnew[mt][1]);
        }

        // exp in registers; write P (tf32) once; partial sums
        float psum[2][2] = {{0.f, 0.f}, {0.f, 0.f}};
        #pragma unroll
        for (int mt = 0; mt < 2; mt++) {
            const int mb = wm * 32 + mt * 16;
            #pragma unroll
            for (int nt = 0; nt < 4; nt++) {
                const int nb = wn * 32 + nt * 8;
                const int c0 = nb + 2 * tg;
                const int r0 = mb + g, r1 = mb + g + 8;
                float p00 = fast_exp(sacc[mt][nt][0] - mnew[mt][0]);
                float p01 = fast_exp(sacc[mt][nt][1] - mnew[mt][0]);
                float p10 = fast_exp(sacc[mt][nt][2] - mnew[mt][1]);
                float p11 = fast_exp(sacc[mt][nt][3] - mnew[mt][1]);
                psum[mt][0] += p00 + p01;
                psum[mt][1] += p10 + p11;
                uint2 w0 = {f2tf32(p00), f2tf32(p01)};
                uint2 w1 = {f2tf32(p10), f2tf32(p11)};
                *(uint2*)&Su[r0 * PS + c0] = w0;
                *(uint2*)&Su[r1 * PS + c0] = w1;
            }
        }
        #pragma unroll
        for (int mt = 0; mt < 2; mt++) {
            psum[mt][0] += __shfl_xor_sync(0xffffffffu, psum[mt][0], 1);
            psum[mt][0] += __shfl_xor_sync(0xffffffffu, psum[mt][0], 2);
            psum[mt][1] += __shfl_xor_sync(0xffffffffu, psum[mt][1], 1);
            psum[mt][1] += __shfl_xor_sync(0xffffffffu, psum[mt][1], 2);
        }
        if (tg == 0) {
            #pragma unroll
            for (int mt = 0; mt < 2; mt++) {
                const int r = wm * 32 + mt * 16 + g;
                psmS[wn * 128 + r]     = psum[mt][0];
                psmS[wn * 128 + r + 8] = psum[mt][1];
            }
        }

        cp_wait<0>();        // V(kt) done (only group in flight)
        __syncthreads();     // bar B: V ready + P & partial sums visible

        // running-stats update (one lane per row)
        if (wn == 0 && tg == 0) {
            #pragma unroll
            for (int mt = 0; mt < 2; mt++) {
                const int r = wm * 32 + mt * 16 + g;
                l_s[r]     = l_s[r]     * fr[mt][0] + psmS[r]       + psmS[128 + r];
                l_s[r + 8] = l_s[r + 8] * fr[mt][1] + psmS[r + 8]   + psmS[128 + r + 8];
                m_s[r]     = mnew[mt][0];
                m_s[r + 8] = mnew[mt][1];
            }
        }

        // prefetch next K (Ks reads all finished at bar B)
        if (kt + 1 < nkt) {
            #pragma unroll
            for (int i = 0; i < 8; i++) {
                const int idx = tid + i * 256;
                const int r = idx >> 5, sg = (idx & 31) * 4;
                cp16(sm_addr(Ks) + (r * PQ + sg) * 4,
                     kbase + (size_t)(k0 + 64 + r) * NQKV + sg);
            }
            cp_commit();
        }

        // ---- O = O*f + P @ V (128x128), warp tile 32x64, 8 k8-steps ----
        #pragma unroll
        for (int mt = 0; mt < 2; mt++)
            #pragma unroll
            for (int nt = 0; nt < 8; nt++) {
                o[mt][nt][0] *= fr[mt][0];  o[mt][nt][1] *= fr[mt][0];
                o[mt][nt][2] *= fr[mt][1];  o[mt][nt][3] *= fr[mt][1];
            }

        #pragma unroll
        for (int ks = 0; ks < 8; ks++) {
            const int kb = ks * 8;
            uint32_t a[2][4];
            ldsm4(a[0], pA[0] + ks * 32);
            ldsm4(a[1], pA[1] + ks * 32);
            #pragma unroll
            for (int nt = 0; nt < 8; nt++) {
                const int nb = wn * 64 + nt * 8;
                uint32_t b0 = Vs[(kb + tg    )*PV + nb + g];
                uint32_t b1 = Vs[(kb + tg + 4)*PV + nb + g];
                #pragma unroll
                for (int mt = 0; mt < 2; mt++)
                    mma8(o[mt][nt], a[mt][0], a[mt][1], a[mt][2], a[mt][3], b0, b1);
            }
        }
        __syncthreads();     // bar C: Vs/Su overwrite protection

        // prefetch next V (overlaps next S-phase)
        if (kt + 1 < nkt) {
            #pragma unroll
            for (int i = 0; i < 8; i++) {
                const int idx = tid + i * 256;
                const int r = idx >> 5, sg = (idx & 31) * 4;
                cp16(sm_addr(Vs) + (r * PV + sg) * 4,
                     vbase + (size_t)(k0 + 64 + r) * NQKV + sg);
            }
            cp_commit();
        }
    }

    __syncthreads();
    // final write: o / l, tf32-rounded for the proj GEMM's raw-bits path
    #pragma unroll
    for (int mt = 0; mt < 2; mt++) {
        const int mb = wm * 32 + mt * 16;
        const float inv0 = 1.f / l_s[mb + g];
        const float inv1 = 1.f / l_s[mb + g + 8];
        #pragma unroll
        for (int nt = 0; nt < 8; nt++) {
            const int col = wn * 64 + nt * 8 + 2 * tg;
            size_t row0 = (size_t)(b * SEQ + q0 + mb + g) * H + h * HD + col;
            size_t row1 = (size_t)(b * SEQ + q0 + mb + g + 8) * H + h * HD + col;
            float2 r0 = {__uint_as_float(f2tf32(o[mt][nt][0] * inv0)),
                         __uint_as_float(f2tf32(o[mt][nt][1] * inv0))};
            float2 r1 = {__uint_as_float(f2tf32(o[mt][nt][2] * inv1)),
                         __uint_as_float(f2tf32(o[mt][nt][3] * inv1))};
            *(float2*)(out + row0) = r0;
            *(float2*)(out + row1) = r1;
        }
    }
}

// ---------------------------------------------------------------------------

extern "C" void kernel_launch(void* const* d_in, const int* in_sizes, int n_in,
                              void* d_out, int out_size)
{
    (void)in_sizes; (void)n_in; (void)out_size;
    const float* x     = (const float*)d_in[0];
    const float* Wqkv  = (const float*)d_in[1];
    const float* bqkv  = (const float*)d_in[2];
    const float* Wproj = (const float*)d_in[3];
    const float* bproj = (const float*)d_in[4];
    float* out = (float*)d_out;

    float *qkv_p, *attn_p;
    uint32_t *xt, *wqt, *wpt;
    cudaGetSymbolAddress((void**)&qkv_p, g_qkv);
    cudaGetSymbolAddress((void**)&attn_p, g_attn);
    cudaGetSymbolAddress((void**)&xt, g_xt);
    cudaGetSymbolAddress((void**)&wqt, g_wqt);
    cudaGetSymbolAddress((void**)&wpt, g_wpt);

    cudaFuncSetAttribute(mqa_attn_tf32, cudaFuncAttributeMaxDynamicSharedMemorySize,
                         ATTN_SMEM_BYTES);
    cudaFuncSetAttribute(gemm_tf32ca<true>, cudaFuncAttributeMaxDynamicSharedMemorySize,
                         GEMM_SMEM_BYTES);
    cudaFuncSetAttribute(gemm_tf32ca<false>, cudaFuncAttributeMaxDynamicSharedMemorySize,
                         GEMM_SMEM_BYTES);

    // 0) pre-round + pre-transpose
    round_tf32<<<(MROWS * H / 4 + 255) / 256, 256>>>(x, xt, MROWS * H / 4);
    transpose_round<<<dim3(NQKV / 32, H / 32), 256>>>(Wqkv, wqt, H, NQKV);
    transpose_round<<<dim3(H / 32, H / 32), 256>>>(Wproj, wpt, H, H);

    // 1) QKV GEMM (256x128 tiles, 3-stage cp.async; output tf32-rounded)
    gemm_tf32ca<true><<<dim3(NQKV / 128, MROWS / 256), 512, GEMM_SMEM_BYTES>>>(
        xt, wqt, bqkv, qkv_p, H, NQKV);

    // 2) causal MQA flash attention (in-register pair softmax)
    mqa_attn_tf32<<<dim3(SEQ / 128, NH, BATCH), 256, ATTN_SMEM_BYTES>>>(qkv_p, attn_p);

    // 3) proj GEMM -> d_out (fp32 output, no rounding)
    gemm_tf32ca<false><<<dim3(H / 128, MROWS / 256), 512, GEMM_SMEM_BYTES>>>(
        (const uint32_t*)attn_p, wpt, bproj, out, H, H);
}